// round 4
// baseline (speedup 1.0000x reference)
#include <cuda_runtime.h>
#include <math.h>

// Problem constants
#define Bb 512
#define Ss 1024
#define Ff 64
#define Ll 128
#define Gg 512   // 4*L
#define BT 4     // batch rows per CTA

typedef unsigned long long ull;

// ------------------------- device scratch -------------------------
// gx[b][t][gate] = x[b,t,:] @ W_ih_enc^T + (b_ih_enc + b_hh_enc)   (1 GB)
__device__ float g_gx[(size_t)Bb * Ss * Gg];
__device__ float g_weff[Gg * Ll];   // W_hh_dec + W_ih_dec @ W_dense
__device__ float g_benc[Gg];
__device__ float g_beff[Gg];
__device__ float g_hn[Bb * Ll];
__device__ float g_cn[Bb * Ll];

// ------------------------- helpers -------------------------
__device__ __forceinline__ ull pk(float x, float y) {
    ull r;
    asm("mov.b64 %0, {%1, %2};" : "=l"(r) : "f"(x), "f"(y));
    return r;
}
__device__ __forceinline__ void upk(ull v, float& x, float& y) {
    asm("mov.b64 {%0, %1}, %2;" : "=f"(x), "=f"(y) : "l"(v));
}
// packed fp32x2 FMA (exact fp32 RN per lane) — 2 FMA per instruction
__device__ __forceinline__ void fma2(ull& d, ull a, ull b) {
    asm("fma.rn.f32x2 %0, %1, %2, %0;" : "+l"(d) : "l"(a), "l"(b));
}
__device__ __forceinline__ float sigf(float x) {
    return 1.0f / (1.0f + expf(-x));
}

// ------------------------- setup: fold decoder matrices -------------------------
// W_eff[j][k] = W_hh_dec[j][k] + sum_m W_ih_dec[j][m] * W_dense[m][k]
// b_eff[j]    = b_ih_dec[j] + b_hh_dec[j] + sum_m W_ih_dec[j][m] * b_dense[m]
// b_enc[j]    = b_ih_enc[j] + b_hh_enc[j]
__global__ void setup_kernel(const float* __restrict__ Wih_d,
                             const float* __restrict__ Whh_d,
                             const float* __restrict__ bih_d,
                             const float* __restrict__ bhh_d,
                             const float* __restrict__ Wdn,
                             const float* __restrict__ bdn,
                             const float* __restrict__ bih_e,
                             const float* __restrict__ bhh_e) {
    int j = blockIdx.x;   // gate 0..511
    int k = threadIdx.x;  // latent 0..127
    float s = 0.0f;
    for (int m = 0; m < Ff; m++) s += Wih_d[j * Ff + m] * Wdn[m * Ll + k];
    g_weff[j * Ll + k] = Whh_d[j * Ll + k] + s;
    if (k == 0) {
        float bs = bih_d[j] + bhh_d[j];
        for (int m = 0; m < Ff; m++) bs += Wih_d[j * Ff + m] * bdn[m];
        g_beff[j] = bs;
        g_benc[j] = bih_e[j] + bhh_e[j];
    }
}

// ------------------------- x-projection GEMM -------------------------
// gx[row][j] = b_enc[j] + sum_m x[row][m] * W_ih_enc[j][m],  row = b*S+t
// Tile: 16 rows x 512 gates per CTA. W_ih fully in smem, packed for LDS.128.
__global__ void __launch_bounds__(512, 1)
xproj_kernel(const float* __restrict__ x, const float* __restrict__ Wih) {
    extern __shared__ char smraw[];
    ulonglong2* Wsm = (ulonglong2*)smraw;              // [16][512] float4 = 128KB
    float* xs = (float*)(smraw + 16 * 512 * 16);       // [16][64] = 4KB
    const int j = threadIdx.x;

    // thread j stages W_ih row j (64 floats = 16 float4) into packed smem
    const float4* wrow = (const float4*)(Wih + j * Ff);
#pragma unroll
    for (int kg = 0; kg < 16; kg++)
        ((float4*)Wsm)[kg * 512 + j] = wrow[kg];

    const float bv = g_benc[j];
    const int row0 = blockIdx.x * 16;

    // stage 16 contiguous x rows (16*64 floats = 256 float4)
    if (j < 256)
        ((float4*)xs)[j] = ((const float4*)x)[row0 * 16 + j];
    __syncthreads();

    ull acc[16];
#pragma unroll
    for (int r = 0; r < 16; r++) acc[r] = 0ull;

#pragma unroll
    for (int kg = 0; kg < 16; kg++) {
        ulonglong2 w = Wsm[kg * 512 + j];
#pragma unroll
        for (int r = 0; r < 16; r++) {
            ulonglong2 hh = *(const ulonglong2*)(xs + r * Ff + kg * 4);
            fma2(acc[r], hh.x, w.x);
            fma2(acc[r], hh.y, w.y);
        }
    }
#pragma unroll
    for (int r = 0; r < 16; r++) {
        float lo, hi;
        upk(acc[r], lo, hi);
        g_gx[(row0 + r) * Gg + j] = lo + hi + bv;
    }
}

// ------------------------- persistent encoder recurrence -------------------------
// One CTA = 4 batch rows, 1024 steps. Thread j = gate j.
// W_hh row j: cols 0..47 in registers (24 f32x2), cols 48..127 in smem.
__global__ void __launch_bounds__(512, 1)
enc_kernel(const float* __restrict__ Whh) {
    extern __shared__ char smraw[];
    ulonglong2* Wsm = (ulonglong2*)smraw;              // [20][512] float4 = 163840B
    float* hs = (float*)(smraw + 20 * 512 * 16);       // [4][128]
    float* gs = hs + BT * Ll;                          // [4][512]
    const int j = threadIdx.x;
    const int b0 = blockIdx.x * BT;

    ull Wr[24];
    const float4* wrow = (const float4*)(Whh + j * Ll);
#pragma unroll
    for (int q = 0; q < 12; q++) {
        float4 v = wrow[q];
        Wr[2 * q] = pk(v.x, v.y);
        Wr[2 * q + 1] = pk(v.z, v.w);
    }
#pragma unroll
    for (int kg = 0; kg < 20; kg++)
        ((float4*)Wsm)[kg * 512 + j] = wrow[12 + kg];

    const int r2 = j >> 7, l2 = j & 127;
    float c = 0.0f;
    hs[j] = 0.0f;
    __syncthreads();

    for (int t = 0; t < Ss; t++) {
        // prefetch precomputed x-gates (consumed only at finalize)
        float gxv[BT];
#pragma unroll
        for (int r = 0; r < BT; r++)
            gxv[r] = g_gx[((b0 + r) * Ss + t) * Gg + j];

        ull acc[BT] = {0ull, 0ull, 0ull, 0ull};
        // register half of W (k = 0..47)
#pragma unroll
        for (int r = 0; r < BT; r++) {
            const ulonglong2* h2 = (const ulonglong2*)(hs + r * Ll);
#pragma unroll
            for (int q = 0; q < 12; q++) {
                ulonglong2 hh = h2[q];
                fma2(acc[r], hh.x, Wr[2 * q]);
                fma2(acc[r], hh.y, Wr[2 * q + 1]);
            }
        }
        // smem half of W (k = 48..127), W load amortized over 4 rows
#pragma unroll
        for (int kg = 0; kg < 20; kg++) {
            ulonglong2 w = Wsm[kg * 512 + j];
#pragma unroll
            for (int r = 0; r < BT; r++) {
                ulonglong2 hh = *(const ulonglong2*)(hs + r * Ll + 48 + kg * 4);
                fma2(acc[r], hh.x, w.x);
                fma2(acc[r], hh.y, w.y);
            }
        }
#pragma unroll
        for (int r = 0; r < BT; r++) {
            float lo, hi;
            upk(acc[r], lo, hi);
            gs[r * Gg + j] = lo + hi + gxv[r];
        }
        __syncthreads();
        // elementwise cell update: thread <-> (r2, l2), c stays in register
        {
            float vi = gs[r2 * Gg + l2];
            float vf = gs[r2 * Gg + 128 + l2];
            float vg = gs[r2 * Gg + 256 + l2];
            float vo = gs[r2 * Gg + 384 + l2];
            c = sigf(vf) * c + sigf(vi) * tanhf(vg);
            hs[j] = sigf(vo) * tanhf(c);
        }
        __syncthreads();
    }
    g_hn[(b0 + r2) * Ll + l2] = hs[j];
    g_cn[(b0 + r2) * Ll + l2] = c;
}

// ------------------------- persistent decoder recurrence -------------------------
// Pure recurrence on W_eff; per step also emits out = h @ W_dense^T + b_dense
// written to the flipped sequence position.
__global__ void __launch_bounds__(512, 1)
dec_kernel(const float* __restrict__ Wdn, const float* __restrict__ bdn,
           float* __restrict__ out) {
    extern __shared__ char smraw[];
    ulonglong2* Wsm = (ulonglong2*)smraw;                       // 163840B
    float* hs = (float*)(smraw + 163840);                       // [4][128]
    float* gs = hs + BT * Ll;                                   // [4][512]
    ull* Wdu = (ull*)(smraw + 163840 + 2048 + 8192);            // [64][64] f32x2 = 32768B
    float* bd = (float*)(smraw + 163840 + 2048 + 8192 + 32768); // [64]
    const int j = threadIdx.x;
    const int b0 = blockIdx.x * BT;

    ull Wr[24];
    const float4* wrow = (const float4*)(g_weff + j * Ll);
#pragma unroll
    for (int q = 0; q < 12; q++) {
        float4 v = wrow[q];
        Wr[2 * q] = pk(v.x, v.y);
        Wr[2 * q + 1] = pk(v.z, v.w);
    }
#pragma unroll
    for (int kg = 0; kg < 20; kg++)
        ((float4*)Wsm)[kg * 512 + j] = wrow[12 + kg];

    // pack W_dense as Wdu[lp][f] = {W_dense[f][2lp], W_dense[f][2lp+1]}
#pragma unroll
    for (int i = 0; i < 8; i++) {
        int e = j + i * 512;
        int lp = e >> 6, f = e & 63;
        float2 v = *(const float2*)(Wdn + f * Ll + 2 * lp);
        Wdu[lp * 64 + f] = pk(v.x, v.y);
    }
    if (j < Ff) bd[j] = bdn[j];

    const float beff = g_beff[j];
    const int r2 = j >> 7, l2 = j & 127;
    float c = g_cn[(b0 + r2) * Ll + l2];
    hs[j] = g_hn[(b0 + r2) * Ll + l2];
    __syncthreads();

    for (int t = 0; t < Ss; t++) {
        ull acc[BT] = {0ull, 0ull, 0ull, 0ull};
#pragma unroll
        for (int r = 0; r < BT; r++) {
            const ulonglong2* h2 = (const ulonglong2*)(hs + r * Ll);
#pragma unroll
            for (int q = 0; q < 12; q++) {
                ulonglong2 hh = h2[q];
                fma2(acc[r], hh.x, Wr[2 * q]);
                fma2(acc[r], hh.y, Wr[2 * q + 1]);
            }
        }
#pragma unroll
        for (int kg = 0; kg < 20; kg++) {
            ulonglong2 w = Wsm[kg * 512 + j];
#pragma unroll
            for (int r = 0; r < BT; r++) {
                ulonglong2 hh = *(const ulonglong2*)(hs + r * Ll + 48 + kg * 4);
                fma2(acc[r], hh.x, w.x);
                fma2(acc[r], hh.y, w.y);
            }
        }
#pragma unroll
        for (int r = 0; r < BT; r++) {
            float lo, hi;
            upk(acc[r], lo, hi);
            gs[r * Gg + j] = lo + hi + beff;
        }
        // dense read-out for step t-1 (hs still holds h_{t-1}); flipped index S-t
        if (t > 0 && j < 256) {
            int rr = j >> 6, f = j & 63;
            ull a = 0ull;
            const ulonglong2* h2 = (const ulonglong2*)(hs + rr * Ll);
#pragma unroll
            for (int q = 0; q < 32; q++) {
                ulonglong2 hh = h2[q];
                fma2(a, hh.x, Wdu[(2 * q) * 64 + f]);
                fma2(a, hh.y, Wdu[(2 * q + 1) * 64 + f]);
            }
            float lo, hi;
            upk(a, lo, hi);
            out[((b0 + rr) * Ss + (Ss - t)) * Ff + f] = lo + hi + bd[f];
        }
        __syncthreads();
        {
            float vi = gs[r2 * Gg + l2];
            float vf = gs[r2 * Gg + 128 + l2];
            float vg = gs[r2 * Gg + 256 + l2];
            float vo = gs[r2 * Gg + 384 + l2];
            c = sigf(vf) * c + sigf(vi) * tanhf(vg);
            hs[j] = sigf(vo) * tanhf(c);
        }
        __syncthreads();
    }
    // final step's read-out (decoder step S-1 -> output position 0)
    if (j < 256) {
        int rr = j >> 6, f = j & 63;
        ull a = 0ull;
        const ulonglong2* h2 = (const ulonglong2*)(hs + rr * Ll);
#pragma unroll
        for (int q = 0; q < 32; q++) {
            ulonglong2 hh = h2[q];
            fma2(a, hh.x, Wdu[(2 * q) * 64 + f]);
            fma2(a, hh.y, Wdu[(2 * q + 1) * 64 + f]);
        }
        float lo, hi;
        upk(a, lo, hi);
        out[((b0 + rr) * Ss + 0) * Ff + f] = lo + hi + bd[f];
    }
}

// ------------------------- launch -------------------------
extern "C" void kernel_launch(void* const* d_in, const int* in_sizes, int n_in,
                              void* d_out, int out_size) {
    const float* x     = (const float*)d_in[0];
    const float* Wih_e = (const float*)d_in[1];
    const float* Whh_e = (const float*)d_in[2];
    const float* bih_e = (const float*)d_in[3];
    const float* bhh_e = (const float*)d_in[4];
    const float* Wih_d = (const float*)d_in[5];
    const float* Whh_d = (const float*)d_in[6];
    const float* bih_d = (const float*)d_in[7];
    const float* bhh_d = (const float*)d_in[8];
    const float* Wdn   = (const float*)d_in[9];
    const float* bdn   = (const float*)d_in[10];
    float* out = (float*)d_out;

    const int SM_X = 16 * 512 * 16 + 16 * 64 * 4;                 // 135168
    const int SM_E = 20 * 512 * 16 + BT * Ll * 4 + BT * Gg * 4;   // 174080
    const int SM_D = SM_E + 64 * 64 * 8 + 64 * 4;                 // 207104

    cudaFuncSetAttribute(xproj_kernel, cudaFuncAttributeMaxDynamicSharedMemorySize, SM_X);
    cudaFuncSetAttribute(enc_kernel,   cudaFuncAttributeMaxDynamicSharedMemorySize, SM_E);
    cudaFuncSetAttribute(dec_kernel,   cudaFuncAttributeMaxDynamicSharedMemorySize, SM_D);

    setup_kernel<<<Gg, Ll>>>(Wih_d, Whh_d, bih_d, bhh_d, Wdn, bdn, bih_e, bhh_e);
    xproj_kernel<<<(Bb * Ss) / 16, 512, SM_X>>>(x, Wih_e);
    enc_kernel<<<Bb / BT, 512, SM_E>>>(Whh_e);
    dec_kernel<<<Bb / BT, 512, SM_D>>>(Wdn, bdn, out);
}

// round 5
// speedup vs baseline: 1.1678x; 1.1678x over previous
#include <cuda_runtime.h>
#include <math.h>

// Problem constants
#define Bb 512
#define Ss 1024
#define Ff 64
#define Ll 128
#define Gg 512   // 4*L
#define BT 4     // batch rows per CTA
#define TT 256   // threads per CTA (recurrent kernels): 2 gates per thread

typedef unsigned long long ull;

// ------------------------- device scratch -------------------------
__device__ float g_gx[(size_t)Bb * Ss * Gg];   // x-projection + enc bias (1 GB)
__device__ float g_weff[Gg * Ll];              // W_hh_dec + W_ih_dec @ W_dense
__device__ float g_benc[Gg];
__device__ float g_beff[Gg];
__device__ float g_hn[Bb * Ll];
__device__ float g_cn[Bb * Ll];

// ------------------------- helpers -------------------------
__device__ __forceinline__ ull pk(float x, float y) {
    ull r; asm("mov.b64 %0, {%1, %2};" : "=l"(r) : "f"(x), "f"(y)); return r;
}
__device__ __forceinline__ void upk(ull v, float& x, float& y) {
    asm("mov.b64 {%0, %1}, %2;" : "=f"(x), "=f"(y) : "l"(v));
}
// packed fp32x2 FMA (exact fp32 RN per lane)
__device__ __forceinline__ void fma2(ull& d, ull a, ull b) {
    asm("fma.rn.f32x2 %0, %1, %2, %0;" : "+l"(d) : "l"(a), "l"(b));
}
__device__ __forceinline__ float ex2a(float x) {
    float r; asm("ex2.approx.f32 %0, %1;" : "=f"(r) : "f"(x)); return r;
}
__device__ __forceinline__ float rcpa(float x) {
    float r; asm("rcp.approx.f32 %0, %1;" : "=f"(r) : "f"(x)); return r;
}
__device__ __forceinline__ float fsig(float x) {
    return rcpa(1.0f + ex2a(-1.4426950408889634f * x));
}
__device__ __forceinline__ float ftanh(float x) {
    return fmaf(2.0f, rcpa(1.0f + ex2a(-2.8853900817779268f * x)), -1.0f);
}

// ------------------------- setup: fold decoder matrices -------------------------
__global__ void setup_kernel(const float* __restrict__ Wih_d,
                             const float* __restrict__ Whh_d,
                             const float* __restrict__ bih_d,
                             const float* __restrict__ bhh_d,
                             const float* __restrict__ Wdn,
                             const float* __restrict__ bdn,
                             const float* __restrict__ bih_e,
                             const float* __restrict__ bhh_e) {
    int j = blockIdx.x;   // gate 0..511
    int k = threadIdx.x;  // latent 0..127
    float s = 0.0f;
    for (int m = 0; m < Ff; m++) s += Wih_d[j * Ff + m] * Wdn[m * Ll + k];
    g_weff[j * Ll + k] = Whh_d[j * Ll + k] + s;
    if (k == 0) {
        float bs = bih_d[j] + bhh_d[j];
        for (int m = 0; m < Ff; m++) bs += Wih_d[j * Ff + m] * bdn[m];
        g_beff[j] = bs;
        g_benc[j] = bih_e[j] + bhh_e[j];
    }
}

// ------------------------- x-projection GEMM -------------------------
// gx[row][j] = b_enc[j] + x[row,:] @ W_ih_enc[j,:]; 32 rows x 512 gates per CTA,
// 256 threads, 2 gates/thread, W_ih entirely in smem packed for LDS.128.
__global__ void __launch_bounds__(TT, 1)
xproj_kernel(const float* __restrict__ x, const float* __restrict__ Wih) {
    extern __shared__ char smraw[];
    ulonglong2* Wsm = (ulonglong2*)smraw;            // [16][512] float4 = 128KB
    float* xs = (float*)(smraw + 16 * 512 * 16);     // [32][64] = 8KB
    const int t_ = threadIdx.x;
    const int gA = t_, gB = t_ + 256;

    const float4* wa = (const float4*)(Wih + gA * Ff);
    const float4* wb = (const float4*)(Wih + gB * Ff);
#pragma unroll
    for (int kg = 0; kg < 16; kg++) {
        ((float4*)Wsm)[kg * 512 + gA] = wa[kg];
        ((float4*)Wsm)[kg * 512 + gB] = wb[kg];
    }
    const float bA = g_benc[gA], bB = g_benc[gB];
    const size_t row0 = (size_t)blockIdx.x * 32;

    // stage 32 x rows (32*64 floats = 512 float4)
    ((float4*)xs)[t_]       = ((const float4*)x)[row0 * 16 + t_];
    ((float4*)xs)[t_ + 256] = ((const float4*)x)[row0 * 16 + t_ + 256];
    __syncthreads();

    ull aA[32], aB[32];
#pragma unroll
    for (int r = 0; r < 32; r++) { aA[r] = 0ull; aB[r] = 0ull; }

#pragma unroll 4
    for (int kg = 0; kg < 16; kg++) {
        ulonglong2 wAv = Wsm[kg * 512 + gA];
        ulonglong2 wBv = Wsm[kg * 512 + gB];
#pragma unroll
        for (int r = 0; r < 32; r++) {
            ulonglong2 hh = *(const ulonglong2*)(xs + r * Ff + 4 * kg);
            fma2(aA[r], hh.x, wAv.x); fma2(aA[r], hh.y, wAv.y);
            fma2(aB[r], hh.x, wBv.x); fma2(aB[r], hh.y, wBv.y);
        }
    }
#pragma unroll
    for (int r = 0; r < 32; r++) {
        float lo, hi;
        upk(aA[r], lo, hi); g_gx[(row0 + r) * Gg + gA] = lo + hi + bA;
        upk(aB[r], lo, hi); g_gx[(row0 + r) * Gg + gB] = lo + hi + bB;
    }
}

// ------------------------- persistent encoder recurrence -------------------------
// CTA = 4 batch rows, 1024 steps, 256 threads. Thread t owns gates t and t+256:
//   t <  128: (i, g) gates of latent l=t       -> writes us = sig(i)*tanh(g)
//   t >= 128: (f, o) gates of latent l=t-128   -> owns c, writes h
// W rows: cols [0,64) in registers (32 f32x2 per gate), cols [64,128) streamed
// from smem (load amortized over 4 batch rows).
__global__ void __launch_bounds__(TT, 1)
enc_kernel(const float* __restrict__ Whh) {
    extern __shared__ char smraw[];
    ulonglong2* Wsm = (ulonglong2*)smraw;            // [16][512] float4 = 128KB
    float* hs = (float*)(smraw + 16 * 512 * 16);     // [4][128]
    float* us = hs + BT * Ll;                        // [4][128]
    const int t_ = threadIdx.x;
    const int b0 = blockIdx.x * BT;
    const int gA = t_, gB = t_ + 256;

    ull WrA[32], WrB[32];
    {
        const float4* wa = (const float4*)(Whh + gA * Ll);
        const float4* wb = (const float4*)(Whh + gB * Ll);
#pragma unroll
        for (int q = 0; q < 16; q++) {
            float4 v = wa[q]; WrA[2 * q] = pk(v.x, v.y); WrA[2 * q + 1] = pk(v.z, v.w);
            float4 u = wb[q]; WrB[2 * q] = pk(u.x, u.y); WrB[2 * q + 1] = pk(u.z, u.w);
        }
#pragma unroll
        for (int kg = 0; kg < 16; kg++) {
            ((float4*)Wsm)[kg * 512 + gA] = wa[16 + kg];
            ((float4*)Wsm)[kg * 512 + gB] = wb[16 + kg];
        }
    }
    hs[t_] = 0.0f; hs[t_ + 256] = 0.0f;
    const bool isFO = (t_ >= 128);
    const int l = t_ & 127;
    float cst[BT] = {0.f, 0.f, 0.f, 0.f};
    __syncthreads();

    for (int t = 0; t < Ss; t++) {
        float gxA[BT], gxB[BT];
#pragma unroll
        for (int r = 0; r < BT; r++) {
            const float* gxp = g_gx + ((size_t)(b0 + r) * Ss + t) * Gg;
            gxA[r] = gxp[gA]; gxB[r] = gxp[gB];
        }
        ull aA[BT] = {0ull, 0ull, 0ull, 0ull};
        ull aB[BT] = {0ull, 0ull, 0ull, 0ull};
        // register half of W (cols 0..63)
#pragma unroll
        for (int q = 0; q < 16; q++) {
#pragma unroll
            for (int r = 0; r < BT; r++) {
                ulonglong2 hh = *(const ulonglong2*)(hs + r * Ll + 4 * q);
                fma2(aA[r], hh.x, WrA[2 * q]); fma2(aA[r], hh.y, WrA[2 * q + 1]);
                fma2(aB[r], hh.x, WrB[2 * q]); fma2(aB[r], hh.y, WrB[2 * q + 1]);
            }
        }
        // smem half of W (cols 64..127)
#pragma unroll
        for (int kg = 0; kg < 16; kg++) {
            ulonglong2 wAv = Wsm[kg * 512 + gA];
            ulonglong2 wBv = Wsm[kg * 512 + gB];
#pragma unroll
            for (int r = 0; r < BT; r++) {
                ulonglong2 hh = *(const ulonglong2*)(hs + r * Ll + 64 + 4 * kg);
                fma2(aA[r], hh.x, wAv.x); fma2(aA[r], hh.y, wAv.y);
                fma2(aB[r], hh.x, wBv.x); fma2(aB[r], hh.y, wBv.y);
            }
        }
        float sf[BT], so[BT];
#pragma unroll
        for (int r = 0; r < BT; r++) {
            float lo, hi, vA, vB;
            upk(aA[r], lo, hi); vA = lo + hi + gxA[r];
            upk(aB[r], lo, hi); vB = lo + hi + gxB[r];
            if (!isFO) {
                us[r * Ll + l] = fsig(vA) * ftanh(vB);   // sig(i)*tanh(g)
            } else {
                sf[r] = fsig(vA); so[r] = fsig(vB);      // sig(f), sig(o)
            }
        }
        __syncthreads();
        if (isFO) {
#pragma unroll
            for (int r = 0; r < BT; r++) {
                cst[r] = sf[r] * cst[r] + us[r * Ll + l];
                hs[r * Ll + l] = so[r] * ftanh(cst[r]);
            }
        }
        __syncthreads();
    }
    if (isFO) {
#pragma unroll
        for (int r = 0; r < BT; r++) {
            g_hn[(b0 + r) * Ll + l] = hs[r * Ll + l];
            g_cn[(b0 + r) * Ll + l] = cst[r];
        }
    }
}

// ------------------------- persistent decoder recurrence -------------------------
// Same structure on W_eff; per step emits out = h @ W_dense^T + b_dense at the
// flipped position. W_dense held in registers, quad-partitioned over latent dim,
// reduced with shfl_xor within each 4-lane quad.
__global__ void __launch_bounds__(TT, 1)
dec_kernel(const float* __restrict__ Wdn, const float* __restrict__ bdn,
           float* __restrict__ out) {
    extern __shared__ char smraw[];
    ulonglong2* Wsm = (ulonglong2*)smraw;            // 128KB
    float* hs = (float*)(smraw + 16 * 512 * 16);     // [4][128]
    float* us = hs + BT * Ll;                        // [4][128]
    const int t_ = threadIdx.x;
    const int b0 = blockIdx.x * BT;
    const int gA = t_, gB = t_ + 256;

    ull WrA[32], WrB[32];
    {
        const float4* wa = (const float4*)(g_weff + gA * Ll);
        const float4* wb = (const float4*)(g_weff + gB * Ll);
#pragma unroll
        for (int q = 0; q < 16; q++) {
            float4 v = wa[q]; WrA[2 * q] = pk(v.x, v.y); WrA[2 * q + 1] = pk(v.z, v.w);
            float4 u = wb[q]; WrB[2 * q] = pk(u.x, u.y); WrB[2 * q + 1] = pk(u.z, u.w);
        }
#pragma unroll
        for (int kg = 0; kg < 16; kg++) {
            ((float4*)Wsm)[kg * 512 + gA] = wa[16 + kg];
            ((float4*)Wsm)[kg * 512 + gB] = wb[16 + kg];
        }
    }
    // dense read-out: thread owns W_dense[fd][32*pd .. 32*pd+32) in registers
    const int fd = t_ >> 2, pd = t_ & 3;
    ull Wd[16];
    {
        const float4* wd = (const float4*)(Wdn + fd * Ll + 32 * pd);
#pragma unroll
        for (int i = 0; i < 8; i++) {
            float4 v = wd[i]; Wd[2 * i] = pk(v.x, v.y); Wd[2 * i + 1] = pk(v.z, v.w);
        }
    }
    const float bdv = bdn[fd];
    const float beA = g_beff[gA], beB = g_beff[gB];

    const bool isFO = (t_ >= 128);
    const int l = t_ & 127;
    // init h, c from encoder
    {
        int e1 = t_, e2 = t_ + 256;
        hs[e1] = g_hn[(b0 + (e1 >> 7)) * Ll + (e1 & 127)];
        hs[e2] = g_hn[(b0 + (e2 >> 7)) * Ll + (e2 & 127)];
    }
    float cst[BT];
#pragma unroll
    for (int r = 0; r < BT; r++) cst[r] = g_cn[(b0 + r) * Ll + l];  // used only by isFO
    __syncthreads();

    for (int t = 0; t < Ss; t++) {
        // dense read-out of current h (= H_t) -> out position S - t, for t >= 1
        if (t > 0) {
            float s[BT];
#pragma unroll
            for (int r = 0; r < BT; r++) {
                ull a = 0ull;
#pragma unroll
                for (int i = 0; i < 8; i++) {
                    ulonglong2 hh = *(const ulonglong2*)(hs + r * Ll + 32 * pd + 4 * i);
                    fma2(a, hh.x, Wd[2 * i]); fma2(a, hh.y, Wd[2 * i + 1]);
                }
                float lo, hi; upk(a, lo, hi); s[r] = lo + hi;
            }
#pragma unroll
            for (int r = 0; r < BT; r++) {
                s[r] += __shfl_xor_sync(0xffffffffu, s[r], 1);
                s[r] += __shfl_xor_sync(0xffffffffu, s[r], 2);
            }
            out[((size_t)(b0 + pd) * Ss + (Ss - t)) * Ff + fd] = s[pd] + bdv;
        }
        ull aA[BT] = {0ull, 0ull, 0ull, 0ull};
        ull aB[BT] = {0ull, 0ull, 0ull, 0ull};
#pragma unroll
        for (int q = 0; q < 16; q++) {
#pragma unroll
            for (int r = 0; r < BT; r++) {
                ulonglong2 hh = *(const ulonglong2*)(hs + r * Ll + 4 * q);
                fma2(aA[r], hh.x, WrA[2 * q]); fma2(aA[r], hh.y, WrA[2 * q + 1]);
                fma2(aB[r], hh.x, WrB[2 * q]); fma2(aB[r], hh.y, WrB[2 * q + 1]);
            }
        }
#pragma unroll
        for (int kg = 0; kg < 16; kg++) {
            ulonglong2 wAv = Wsm[kg * 512 + gA];
            ulonglong2 wBv = Wsm[kg * 512 + gB];
#pragma unroll
            for (int r = 0; r < BT; r++) {
                ulonglong2 hh = *(const ulonglong2*)(hs + r * Ll + 64 + 4 * kg);
                fma2(aA[r], hh.x, wAv.x); fma2(aA[r], hh.y, wAv.y);
                fma2(aB[r], hh.x, wBv.x); fma2(aB[r], hh.y, wBv.y);
            }
        }
        float sf[BT], so[BT];
#pragma unroll
        for (int r = 0; r < BT; r++) {
            float lo, hi, vA, vB;
            upk(aA[r], lo, hi); vA = lo + hi + beA;
            upk(aB[r], lo, hi); vB = lo + hi + beB;
            if (!isFO) {
                us[r * Ll + l] = fsig(vA) * ftanh(vB);
            } else {
                sf[r] = fsig(vA); so[r] = fsig(vB);
            }
        }
        __syncthreads();
        if (isFO) {
#pragma unroll
            for (int r = 0; r < BT; r++) {
                cst[r] = sf[r] * cst[r] + us[r * Ll + l];
                hs[r * Ll + l] = so[r] * ftanh(cst[r]);
            }
        }
        __syncthreads();
    }
    // final dense read-out (H_S) -> out position 0
    {
        float s[BT];
#pragma unroll
        for (int r = 0; r < BT; r++) {
            ull a = 0ull;
#pragma unroll
            for (int i = 0; i < 8; i++) {
                ulonglong2 hh = *(const ulonglong2*)(hs + r * Ll + 32 * pd + 4 * i);
                fma2(a, hh.x, Wd[2 * i]); fma2(a, hh.y, Wd[2 * i + 1]);
            }
            float lo, hi; upk(a, lo, hi); s[r] = lo + hi;
        }
#pragma unroll
        for (int r = 0; r < BT; r++) {
            s[r] += __shfl_xor_sync(0xffffffffu, s[r], 1);
            s[r] += __shfl_xor_sync(0xffffffffu, s[r], 2);
        }
        out[((size_t)(b0 + pd) * Ss + 0) * Ff + fd] = s[pd] + bdv;
    }
}

// ------------------------- launch -------------------------
extern "C" void kernel_launch(void* const* d_in, const int* in_sizes, int n_in,
                              void* d_out, int out_size) {
    const float* x     = (const float*)d_in[0];
    const float* Wih_e = (const float*)d_in[1];
    const float* Whh_e = (const float*)d_in[2];
    const float* bih_e = (const float*)d_in[3];
    const float* bhh_e = (const float*)d_in[4];
    const float* Wih_d = (const float*)d_in[5];
    const float* Whh_d = (const float*)d_in[6];
    const float* bih_d = (const float*)d_in[7];
    const float* bhh_d = (const float*)d_in[8];
    const float* Wdn   = (const float*)d_in[9];
    const float* bdn   = (const float*)d_in[10];
    float* out = (float*)d_out;

    const int SM_X = 16 * 512 * 16 + 32 * 64 * 4;                   // 139264
    const int SM_R = 16 * 512 * 16 + 2 * BT * Ll * 4;               // 135168

    cudaFuncSetAttribute(xproj_kernel, cudaFuncAttributeMaxDynamicSharedMemorySize, SM_X);
    cudaFuncSetAttribute(enc_kernel,   cudaFuncAttributeMaxDynamicSharedMemorySize, SM_R);
    cudaFuncSetAttribute(dec_kernel,   cudaFuncAttributeMaxDynamicSharedMemorySize, SM_R);

    setup_kernel<<<Gg, Ll>>>(Wih_d, Whh_d, bih_d, bhh_d, Wdn, bdn, bih_e, bhh_e);
    xproj_kernel<<<(Bb * Ss) / 32, TT, SM_X>>>(x, Wih_e);
    enc_kernel<<<Bb / BT, TT, SM_R>>>(Whh_e);
    dec_kernel<<<Bb / BT, TT, SM_R>>>(Wdn, bdn, out);
}

// round 6
// speedup vs baseline: 1.1689x; 1.0009x over previous
#include <cuda_runtime.h>
#include <math.h>

// Problem constants
#define Bb 512
#define Ss 1024
#define Ff 64
#define Ll 128
#define Gg 512   // 4*L
#define BT 4     // batch rows per CTA
#define TT 256   // threads per CTA (recurrent kernels): 2 gates per thread

typedef unsigned long long ull;

// ------------------------- device scratch -------------------------
__device__ float g_gx[(size_t)Bb * Ss * Gg];   // x-projection + enc bias (1 GB)
__device__ float g_weff[Gg * Ll];              // W_hh_dec + W_ih_dec @ W_dense
__device__ float g_benc[Gg];
__device__ float g_beff[Gg];
__device__ float g_hn[Bb * Ll];
__device__ float g_cn[Bb * Ll];

// ------------------------- helpers -------------------------
__device__ __forceinline__ ull pk(float x, float y) {
    ull r; asm("mov.b64 %0, {%1, %2};" : "=l"(r) : "f"(x), "f"(y)); return r;
}
__device__ __forceinline__ void upk(ull v, float& x, float& y) {
    asm("mov.b64 {%0, %1}, %2;" : "=f"(x), "=f"(y) : "l"(v));
}
// packed fp32x2 FMA (exact fp32 RN per lane)
__device__ __forceinline__ void fma2(ull& d, ull a, ull b) {
    asm("fma.rn.f32x2 %0, %1, %2, %0;" : "+l"(d) : "l"(a), "l"(b));
}
__device__ __forceinline__ float ex2a(float x) {
    float r; asm("ex2.approx.f32 %0, %1;" : "=f"(r) : "f"(x)); return r;
}
__device__ __forceinline__ float rcpa(float x) {
    float r; asm("rcp.approx.f32 %0, %1;" : "=f"(r) : "f"(x)); return r;
}
__device__ __forceinline__ float fsig(float x) {
    return rcpa(1.0f + ex2a(-1.4426950408889634f * x));
}
__device__ __forceinline__ float ftanh(float x) {
    return fmaf(2.0f, rcpa(1.0f + ex2a(-2.8853900817779268f * x)), -1.0f);
}

// ------------------------- setup: fold decoder matrices -------------------------
__global__ void setup_kernel(const float* __restrict__ Wih_d,
                             const float* __restrict__ Whh_d,
                             const float* __restrict__ bih_d,
                             const float* __restrict__ bhh_d,
                             const float* __restrict__ Wdn,
                             const float* __restrict__ bdn,
                             const float* __restrict__ bih_e,
                             const float* __restrict__ bhh_e) {
    int j = blockIdx.x;   // gate 0..511
    int k = threadIdx.x;  // latent 0..127
    float s = 0.0f;
    for (int m = 0; m < Ff; m++) s += Wih_d[j * Ff + m] * Wdn[m * Ll + k];
    g_weff[j * Ll + k] = Whh_d[j * Ll + k] + s;
    if (k == 0) {
        float bs = bih_d[j] + bhh_d[j];
        for (int m = 0; m < Ff; m++) bs += Wih_d[j * Ff + m] * bdn[m];
        g_beff[j] = bs;
        g_benc[j] = bih_e[j] + bhh_e[j];
    }
}

// ------------------------- x-projection GEMM -------------------------
// gx[row][j] = b_enc[j] + x[row,:] @ W_ih_enc[j,:]; 32 rows x 512 gates per CTA,
// 256 threads, 2 gates/thread, W_ih entirely in smem packed for LDS.128.
__global__ void __launch_bounds__(TT, 1)
xproj_kernel(const float* __restrict__ x, const float* __restrict__ Wih) {
    extern __shared__ char smraw[];
    ulonglong2* Wsm = (ulonglong2*)smraw;            // [16][512] float4 = 128KB
    float* xs = (float*)(smraw + 16 * 512 * 16);     // [32][64] = 8KB
    const int t_ = threadIdx.x;
    const int gA = t_, gB = t_ + 256;

    const float4* wa = (const float4*)(Wih + gA * Ff);
    const float4* wb = (const float4*)(Wih + gB * Ff);
#pragma unroll
    for (int kg = 0; kg < 16; kg++) {
        ((float4*)Wsm)[kg * 512 + gA] = wa[kg];
        ((float4*)Wsm)[kg * 512 + gB] = wb[kg];
    }
    const float bA = g_benc[gA], bB = g_benc[gB];
    const size_t row0 = (size_t)blockIdx.x * 32;

    // stage 32 x rows (32*64 floats = 512 float4)
    ((float4*)xs)[t_]       = ((const float4*)x)[row0 * 16 + t_];
    ((float4*)xs)[t_ + 256] = ((const float4*)x)[row0 * 16 + t_ + 256];
    __syncthreads();

    ull aA[32], aB[32];
#pragma unroll
    for (int r = 0; r < 32; r++) { aA[r] = 0ull; aB[r] = 0ull; }

#pragma unroll 4
    for (int kg = 0; kg < 16; kg++) {
        ulonglong2 wAv = Wsm[kg * 512 + gA];
        ulonglong2 wBv = Wsm[kg * 512 + gB];
#pragma unroll
        for (int r = 0; r < 32; r++) {
            ulonglong2 hh = *(const ulonglong2*)(xs + r * Ff + 4 * kg);
            fma2(aA[r], hh.x, wAv.x); fma2(aA[r], hh.y, wAv.y);
            fma2(aB[r], hh.x, wBv.x); fma2(aB[r], hh.y, wBv.y);
        }
    }
#pragma unroll
    for (int r = 0; r < 32; r++) {
        float lo, hi;
        upk(aA[r], lo, hi); g_gx[(row0 + r) * Gg + gA] = lo + hi + bA;
        upk(aB[r], lo, hi); g_gx[(row0 + r) * Gg + gB] = lo + hi + bB;
    }
}

// ------------------------- persistent encoder recurrence -------------------------
// CTA = 4 batch rows, 1024 steps, 256 threads. Thread t owns gates t and t+256:
//   t <  128: (i, g) gates of latent l=t       -> writes us = sig(i)*tanh(g)
//   t >= 128: (f, o) gates of latent l=t-128   -> owns c, writes h
// W rows: cols [0,64) in registers (32 f32x2 per gate), cols [64,128) streamed
// from smem (load amortized over 4 batch rows).
__global__ void __launch_bounds__(TT, 1)
enc_kernel(const float* __restrict__ Whh) {
    extern __shared__ char smraw[];
    ulonglong2* Wsm = (ulonglong2*)smraw;            // [16][512] float4 = 128KB
    float* hs = (float*)(smraw + 16 * 512 * 16);     // [4][128]
    float* us = hs + BT * Ll;                        // [4][128]
    const int t_ = threadIdx.x;
    const int b0 = blockIdx.x * BT;
    const int gA = t_, gB = t_ + 256;

    ull WrA[32], WrB[32];
    {
        const float4* wa = (const float4*)(Whh + gA * Ll);
        const float4* wb = (const float4*)(Whh + gB * Ll);
#pragma unroll
        for (int q = 0; q < 16; q++) {
            float4 v = wa[q]; WrA[2 * q] = pk(v.x, v.y); WrA[2 * q + 1] = pk(v.z, v.w);
            float4 u = wb[q]; WrB[2 * q] = pk(u.x, u.y); WrB[2 * q + 1] = pk(u.z, u.w);
        }
#pragma unroll
        for (int kg = 0; kg < 16; kg++) {
            ((float4*)Wsm)[kg * 512 + gA] = wa[16 + kg];
            ((float4*)Wsm)[kg * 512 + gB] = wb[16 + kg];
        }
    }
    hs[t_] = 0.0f; hs[t_ + 256] = 0.0f;
    const bool isFO = (t_ >= 128);
    const int l = t_ & 127;
    float cst[BT] = {0.f, 0.f, 0.f, 0.f};
    __syncthreads();

    for (int t = 0; t < Ss; t++) {
        float gxA[BT], gxB[BT];
#pragma unroll
        for (int r = 0; r < BT; r++) {
            const float* gxp = g_gx + ((size_t)(b0 + r) * Ss + t) * Gg;
            gxA[r] = gxp[gA]; gxB[r] = gxp[gB];
        }
        ull aA[BT] = {0ull, 0ull, 0ull, 0ull};
        ull aB[BT] = {0ull, 0ull, 0ull, 0ull};
        // register half of W (cols 0..63)
#pragma unroll
        for (int q = 0; q < 16; q++) {
#pragma unroll
            for (int r = 0; r < BT; r++) {
                ulonglong2 hh = *(const ulonglong2*)(hs + r * Ll + 4 * q);
                fma2(aA[r], hh.x, WrA[2 * q]); fma2(aA[r], hh.y, WrA[2 * q + 1]);
                fma2(aB[r], hh.x, WrB[2 * q]); fma2(aB[r], hh.y, WrB[2 * q + 1]);
            }
        }
        // smem half of W (cols 64..127)
#pragma unroll
        for (int kg = 0; kg < 16; kg++) {
            ulonglong2 wAv = Wsm[kg * 512 + gA];
            ulonglong2 wBv = Wsm[kg * 512 + gB];
#pragma unroll
            for (int r = 0; r < BT; r++) {
                ulonglong2 hh = *(const ulonglong2*)(hs + r * Ll + 64 + 4 * kg);
                fma2(aA[r], hh.x, wAv.x); fma2(aA[r], hh.y, wAv.y);
                fma2(aB[r], hh.x, wBv.x); fma2(aB[r], hh.y, wBv.y);
            }
        }
        float sf[BT], so[BT];
#pragma unroll
        for (int r = 0; r < BT; r++) {
            float lo, hi, vA, vB;
            upk(aA[r], lo, hi); vA = lo + hi + gxA[r];
            upk(aB[r], lo, hi); vB = lo + hi + gxB[r];
            if (!isFO) {
                us[r * Ll + l] = fsig(vA) * ftanh(vB);   // sig(i)*tanh(g)
            } else {
                sf[r] = fsig(vA); so[r] = fsig(vB);      // sig(f), sig(o)
            }
        }
        __syncthreads();
        if (isFO) {
#pragma unroll
            for (int r = 0; r < BT; r++) {
                cst[r] = sf[r] * cst[r] + us[r * Ll + l];
                hs[r * Ll + l] = so[r] * ftanh(cst[r]);
            }
        }
        __syncthreads();
    }
    if (isFO) {
#pragma unroll
        for (int r = 0; r < BT; r++) {
            g_hn[(b0 + r) * Ll + l] = hs[r * Ll + l];
            g_cn[(b0 + r) * Ll + l] = cst[r];
        }
    }
}

// ------------------------- persistent decoder recurrence -------------------------
// Same structure on W_eff; per step emits out = h @ W_dense^T + b_dense at the
// flipped position. W_dense held in registers, quad-partitioned over latent dim,
// reduced with shfl_xor within each 4-lane quad.
__global__ void __launch_bounds__(TT, 1)
dec_kernel(const float* __restrict__ Wdn, const float* __restrict__ bdn,
           float* __restrict__ out) {
    extern __shared__ char smraw[];
    ulonglong2* Wsm = (ulonglong2*)smraw;            // 128KB
    float* hs = (float*)(smraw + 16 * 512 * 16);     // [4][128]
    float* us = hs + BT * Ll;                        // [4][128]
    const int t_ = threadIdx.x;
    const int b0 = blockIdx.x * BT;
    const int gA = t_, gB = t_ + 256;

    ull WrA[32], WrB[32];
    {
        const float4* wa = (const float4*)(g_weff + gA * Ll);
        const float4* wb = (const float4*)(g_weff + gB * Ll);
#pragma unroll
        for (int q = 0; q < 16; q++) {
            float4 v = wa[q]; WrA[2 * q] = pk(v.x, v.y); WrA[2 * q + 1] = pk(v.z, v.w);
            float4 u = wb[q]; WrB[2 * q] = pk(u.x, u.y); WrB[2 * q + 1] = pk(u.z, u.w);
        }
#pragma unroll
        for (int kg = 0; kg < 16; kg++) {
            ((float4*)Wsm)[kg * 512 + gA] = wa[16 + kg];
            ((float4*)Wsm)[kg * 512 + gB] = wb[16 + kg];
        }
    }
    // dense read-out: thread owns W_dense[fd][32*pd .. 32*pd+32) in registers
    const int fd = t_ >> 2, pd = t_ & 3;
    ull Wd[16];
    {
        const float4* wd = (const float4*)(Wdn + fd * Ll + 32 * pd);
#pragma unroll
        for (int i = 0; i < 8; i++) {
            float4 v = wd[i]; Wd[2 * i] = pk(v.x, v.y); Wd[2 * i + 1] = pk(v.z, v.w);
        }
    }
    const float bdv = bdn[fd];
    const float beA = g_beff[gA], beB = g_beff[gB];

    const bool isFO = (t_ >= 128);
    const int l = t_ & 127;
    // init h, c from encoder
    {
        int e1 = t_, e2 = t_ + 256;
        hs[e1] = g_hn[(b0 + (e1 >> 7)) * Ll + (e1 & 127)];
        hs[e2] = g_hn[(b0 + (e2 >> 7)) * Ll + (e2 & 127)];
    }
    float cst[BT];
#pragma unroll
    for (int r = 0; r < BT; r++) cst[r] = g_cn[(b0 + r) * Ll + l];  // used only by isFO
    __syncthreads();

    for (int t = 0; t < Ss; t++) {
        // dense read-out of current h (= H_t) -> out position S - t, for t >= 1
        if (t > 0) {
            float s[BT];
#pragma unroll
            for (int r = 0; r < BT; r++) {
                ull a = 0ull;
#pragma unroll
                for (int i = 0; i < 8; i++) {
                    ulonglong2 hh = *(const ulonglong2*)(hs + r * Ll + 32 * pd + 4 * i);
                    fma2(a, hh.x, Wd[2 * i]); fma2(a, hh.y, Wd[2 * i + 1]);
                }
                float lo, hi; upk(a, lo, hi); s[r] = lo + hi;
            }
#pragma unroll
            for (int r = 0; r < BT; r++) {
                s[r] += __shfl_xor_sync(0xffffffffu, s[r], 1);
                s[r] += __shfl_xor_sync(0xffffffffu, s[r], 2);
            }
            out[((size_t)(b0 + pd) * Ss + (Ss - t)) * Ff + fd] = s[pd] + bdv;
        }
        ull aA[BT] = {0ull, 0ull, 0ull, 0ull};
        ull aB[BT] = {0ull, 0ull, 0ull, 0ull};
#pragma unroll
        for (int q = 0; q < 16; q++) {
#pragma unroll
            for (int r = 0; r < BT; r++) {
                ulonglong2 hh = *(const ulonglong2*)(hs + r * Ll + 4 * q);
                fma2(aA[r], hh.x, WrA[2 * q]); fma2(aA[r], hh.y, WrA[2 * q + 1]);
                fma2(aB[r], hh.x, WrB[2 * q]); fma2(aB[r], hh.y, WrB[2 * q + 1]);
            }
        }
#pragma unroll
        for (int kg = 0; kg < 16; kg++) {
            ulonglong2 wAv = Wsm[kg * 512 + gA];
            ulonglong2 wBv = Wsm[kg * 512 + gB];
#pragma unroll
            for (int r = 0; r < BT; r++) {
                ulonglong2 hh = *(const ulonglong2*)(hs + r * Ll + 64 + 4 * kg);
                fma2(aA[r], hh.x, wAv.x); fma2(aA[r], hh.y, wAv.y);
                fma2(aB[r], hh.x, wBv.x); fma2(aB[r], hh.y, wBv.y);
            }
        }
        float sf[BT], so[BT];
#pragma unroll
        for (int r = 0; r < BT; r++) {
            float lo, hi, vA, vB;
            upk(aA[r], lo, hi); vA = lo + hi + beA;
            upk(aB[r], lo, hi); vB = lo + hi + beB;
            if (!isFO) {
                us[r * Ll + l] = fsig(vA) * ftanh(vB);
            } else {
                sf[r] = fsig(vA); so[r] = fsig(vB);
            }
        }
        __syncthreads();
        if (isFO) {
#pragma unroll
            for (int r = 0; r < BT; r++) {
                cst[r] = sf[r] * cst[r] + us[r * Ll + l];
                hs[r * Ll + l] = so[r] * ftanh(cst[r]);
            }
        }
        __syncthreads();
    }
    // final dense read-out (H_S) -> out position 0
    {
        float s[BT];
#pragma unroll
        for (int r = 0; r < BT; r++) {
            ull a = 0ull;
#pragma unroll
            for (int i = 0; i < 8; i++) {
                ulonglong2 hh = *(const ulonglong2*)(hs + r * Ll + 32 * pd + 4 * i);
                fma2(a, hh.x, Wd[2 * i]); fma2(a, hh.y, Wd[2 * i + 1]);
            }
            float lo, hi; upk(a, lo, hi); s[r] = lo + hi;
        }
#pragma unroll
        for (int r = 0; r < BT; r++) {
            s[r] += __shfl_xor_sync(0xffffffffu, s[r], 1);
            s[r] += __shfl_xor_sync(0xffffffffu, s[r], 2);
        }
        out[((size_t)(b0 + pd) * Ss + 0) * Ff + fd] = s[pd] + bdv;
    }
}

// ------------------------- launch -------------------------
extern "C" void kernel_launch(void* const* d_in, const int* in_sizes, int n_in,
                              void* d_out, int out_size) {
    const float* x     = (const float*)d_in[0];
    const float* Wih_e = (const float*)d_in[1];
    const float* Whh_e = (const float*)d_in[2];
    const float* bih_e = (const float*)d_in[3];
    const float* bhh_e = (const float*)d_in[4];
    const float* Wih_d = (const float*)d_in[5];
    const float* Whh_d = (const float*)d_in[6];
    const float* bih_d = (const float*)d_in[7];
    const float* bhh_d = (const float*)d_in[8];
    const float* Wdn   = (const float*)d_in[9];
    const float* bdn   = (const float*)d_in[10];
    float* out = (float*)d_out;

    const int SM_X = 16 * 512 * 16 + 32 * 64 * 4;                   // 139264
    const int SM_R = 16 * 512 * 16 + 2 * BT * Ll * 4;               // 135168

    cudaFuncSetAttribute(xproj_kernel, cudaFuncAttributeMaxDynamicSharedMemorySize, SM_X);
    cudaFuncSetAttribute(enc_kernel,   cudaFuncAttributeMaxDynamicSharedMemorySize, SM_R);
    cudaFuncSetAttribute(dec_kernel,   cudaFuncAttributeMaxDynamicSharedMemorySize, SM_R);

    setup_kernel<<<Gg, Ll>>>(Wih_d, Whh_d, bih_d, bhh_d, Wdn, bdn, bih_e, bhh_e);
    xproj_kernel<<<(Bb * Ss) / 32, TT, SM_X>>>(x, Wih_e);
    enc_kernel<<<Bb / BT, TT, SM_R>>>(Whh_e);
    dec_kernel<<<Bb / BT, TT, SM_R>>>(Wdn, bdn, out);
}

// round 7
// speedup vs baseline: 1.1696x; 1.0007x over previous
#include <cuda_runtime.h>
#include <math.h>

// Problem constants
#define Bb 512
#define Ss 1024
#define Ff 64
#define Ll 128
#define Gg 512   // 4*L
#define BT 4     // batch rows per CTA
#define TT 256   // threads per CTA (recurrent kernels): 2 gates per thread

typedef unsigned long long ull;

// ------------------------- device scratch -------------------------
__device__ float g_gx[(size_t)Bb * Ss * Gg];   // x-projection + enc bias (1 GB)
__device__ float g_weff[Gg * Ll];              // W_hh_dec + W_ih_dec @ W_dense
__device__ float g_benc[Gg];
__device__ float g_beff[Gg];
__device__ float g_hn[Bb * Ll];
__device__ float g_cn[Bb * Ll];

// ------------------------- helpers -------------------------
__device__ __forceinline__ ull pk(float x, float y) {
    ull r; asm("mov.b64 %0, {%1, %2};" : "=l"(r) : "f"(x), "f"(y)); return r;
}
__device__ __forceinline__ void upk(ull v, float& x, float& y) {
    asm("mov.b64 {%0, %1}, %2;" : "=f"(x), "=f"(y) : "l"(v));
}
// packed fp32x2 FMA (exact fp32 RN per lane)
__device__ __forceinline__ void fma2(ull& d, ull a, ull b) {
    asm("fma.rn.f32x2 %0, %1, %2, %0;" : "+l"(d) : "l"(a), "l"(b));
}
__device__ __forceinline__ float ex2a(float x) {
    float r; asm("ex2.approx.f32 %0, %1;" : "=f"(r) : "f"(x)); return r;
}
__device__ __forceinline__ float rcpa(float x) {
    float r; asm("rcp.approx.f32 %0, %1;" : "=f"(r) : "f"(x)); return r;
}
__device__ __forceinline__ float fsig(float x) {
    return rcpa(1.0f + ex2a(-1.4426950408889634f * x));
}
__device__ __forceinline__ float ftanh(float x) {
    return fmaf(2.0f, rcpa(1.0f + ex2a(-2.8853900817779268f * x)), -1.0f);
}

// ------------------------- setup: fold decoder matrices -------------------------
__global__ void setup_kernel(const float* __restrict__ Wih_d,
                             const float* __restrict__ Whh_d,
                             const float* __restrict__ bih_d,
                             const float* __restrict__ bhh_d,
                             const float* __restrict__ Wdn,
                             const float* __restrict__ bdn,
                             const float* __restrict__ bih_e,
                             const float* __restrict__ bhh_e) {
    int j = blockIdx.x;   // gate 0..511
    int k = threadIdx.x;  // latent 0..127
    float s = 0.0f;
    for (int m = 0; m < Ff; m++) s += Wih_d[j * Ff + m] * Wdn[m * Ll + k];
    g_weff[j * Ll + k] = Whh_d[j * Ll + k] + s;
    if (k == 0) {
        float bs = bih_d[j] + bhh_d[j];
        for (int m = 0; m < Ff; m++) bs += Wih_d[j * Ff + m] * bdn[m];
        g_beff[j] = bs;
        g_benc[j] = bih_e[j] + bhh_e[j];
    }
}

// ------------------------- x-projection GEMM -------------------------
// gx[row][j] = b_enc[j] + x[row,:] @ W_ih_enc[j,:]; 32 rows x 512 gates per CTA,
// 256 threads, 2 gates/thread, W_ih entirely in smem packed for LDS.128.
__global__ void __launch_bounds__(TT, 1)
xproj_kernel(const float* __restrict__ x, const float* __restrict__ Wih) {
    extern __shared__ char smraw[];
    ulonglong2* Wsm = (ulonglong2*)smraw;            // [16][512] float4 = 128KB
    float* xs = (float*)(smraw + 16 * 512 * 16);     // [32][64] = 8KB
    const int t_ = threadIdx.x;
    const int gA = t_, gB = t_ + 256;

    const float4* wa = (const float4*)(Wih + gA * Ff);
    const float4* wb = (const float4*)(Wih + gB * Ff);
#pragma unroll
    for (int kg = 0; kg < 16; kg++) {
        ((float4*)Wsm)[kg * 512 + gA] = wa[kg];
        ((float4*)Wsm)[kg * 512 + gB] = wb[kg];
    }
    const float bA = g_benc[gA], bB = g_benc[gB];
    const size_t row0 = (size_t)blockIdx.x * 32;

    // stage 32 x rows (32*64 floats = 512 float4)
    ((float4*)xs)[t_]       = ((const float4*)x)[row0 * 16 + t_];
    ((float4*)xs)[t_ + 256] = ((const float4*)x)[row0 * 16 + t_ + 256];
    __syncthreads();

    ull aA[32], aB[32];
#pragma unroll
    for (int r = 0; r < 32; r++) { aA[r] = 0ull; aB[r] = 0ull; }

#pragma unroll 4
    for (int kg = 0; kg < 16; kg++) {
        ulonglong2 wAv = Wsm[kg * 512 + gA];
        ulonglong2 wBv = Wsm[kg * 512 + gB];
#pragma unroll
        for (int r = 0; r < 32; r++) {
            ulonglong2 hh = *(const ulonglong2*)(xs + r * Ff + 4 * kg);
            fma2(aA[r], hh.x, wAv.x); fma2(aA[r], hh.y, wAv.y);
            fma2(aB[r], hh.x, wBv.x); fma2(aB[r], hh.y, wBv.y);
        }
    }
#pragma unroll
    for (int r = 0; r < 32; r++) {
        float lo, hi;
        upk(aA[r], lo, hi); g_gx[(row0 + r) * Gg + gA] = lo + hi + bA;
        upk(aB[r], lo, hi); g_gx[(row0 + r) * Gg + gB] = lo + hi + bB;
    }
}

// ------------------------- persistent encoder recurrence -------------------------
// CTA = 4 batch rows, 1024 steps, 256 threads. Thread t owns gates t and t+256:
//   t <  128: (i, g) gates of latent l=t       -> writes us = sig(i)*tanh(g)
//   t >= 128: (f, o) gates of latent l=t-128   -> owns c, writes h
// W rows: cols [0,64) in registers (32 f32x2 per gate), cols [64,128) streamed
// from smem (load amortized over 4 batch rows).
__global__ void __launch_bounds__(TT, 1)
enc_kernel(const float* __restrict__ Whh) {
    extern __shared__ char smraw[];
    ulonglong2* Wsm = (ulonglong2*)smraw;            // [16][512] float4 = 128KB
    float* hs = (float*)(smraw + 16 * 512 * 16);     // [4][128]
    float* us = hs + BT * Ll;                        // [4][128]
    const int t_ = threadIdx.x;
    const int b0 = blockIdx.x * BT;
    const int gA = t_, gB = t_ + 256;

    ull WrA[32], WrB[32];
    {
        const float4* wa = (const float4*)(Whh + gA * Ll);
        const float4* wb = (const float4*)(Whh + gB * Ll);
#pragma unroll
        for (int q = 0; q < 16; q++) {
            float4 v = wa[q]; WrA[2 * q] = pk(v.x, v.y); WrA[2 * q + 1] = pk(v.z, v.w);
            float4 u = wb[q]; WrB[2 * q] = pk(u.x, u.y); WrB[2 * q + 1] = pk(u.z, u.w);
        }
#pragma unroll
        for (int kg = 0; kg < 16; kg++) {
            ((float4*)Wsm)[kg * 512 + gA] = wa[16 + kg];
            ((float4*)Wsm)[kg * 512 + gB] = wb[16 + kg];
        }
    }
    hs[t_] = 0.0f; hs[t_ + 256] = 0.0f;
    const bool isFO = (t_ >= 128);
    const int l = t_ & 127;
    float cst[BT] = {0.f, 0.f, 0.f, 0.f};
    __syncthreads();

    for (int t = 0; t < Ss; t++) {
        float gxA[BT], gxB[BT];
#pragma unroll
        for (int r = 0; r < BT; r++) {
            const float* gxp = g_gx + ((size_t)(b0 + r) * Ss + t) * Gg;
            gxA[r] = gxp[gA]; gxB[r] = gxp[gB];
        }
        ull aA[BT] = {0ull, 0ull, 0ull, 0ull};
        ull aB[BT] = {0ull, 0ull, 0ull, 0ull};
        // register half of W (cols 0..63)
#pragma unroll
        for (int q = 0; q < 16; q++) {
#pragma unroll
            for (int r = 0; r < BT; r++) {
                ulonglong2 hh = *(const ulonglong2*)(hs + r * Ll + 4 * q);
                fma2(aA[r], hh.x, WrA[2 * q]); fma2(aA[r], hh.y, WrA[2 * q + 1]);
                fma2(aB[r], hh.x, WrB[2 * q]); fma2(aB[r], hh.y, WrB[2 * q + 1]);
            }
        }
        // smem half of W (cols 64..127)
#pragma unroll
        for (int kg = 0; kg < 16; kg++) {
            ulonglong2 wAv = Wsm[kg * 512 + gA];
            ulonglong2 wBv = Wsm[kg * 512 + gB];
#pragma unroll
            for (int r = 0; r < BT; r++) {
                ulonglong2 hh = *(const ulonglong2*)(hs + r * Ll + 64 + 4 * kg);
                fma2(aA[r], hh.x, wAv.x); fma2(aA[r], hh.y, wAv.y);
                fma2(aB[r], hh.x, wBv.x); fma2(aB[r], hh.y, wBv.y);
            }
        }
        float sf[BT], so[BT];
#pragma unroll
        for (int r = 0; r < BT; r++) {
            float lo, hi, vA, vB;
            upk(aA[r], lo, hi); vA = lo + hi + gxA[r];
            upk(aB[r], lo, hi); vB = lo + hi + gxB[r];
            if (!isFO) {
                us[r * Ll + l] = fsig(vA) * ftanh(vB);   // sig(i)*tanh(g)
            } else {
                sf[r] = fsig(vA); so[r] = fsig(vB);      // sig(f), sig(o)
            }
        }
        __syncthreads();
        if (isFO) {
#pragma unroll
            for (int r = 0; r < BT; r++) {
                cst[r] = sf[r] * cst[r] + us[r * Ll + l];
                hs[r * Ll + l] = so[r] * ftanh(cst[r]);
            }
        }
        __syncthreads();
    }
    if (isFO) {
#pragma unroll
        for (int r = 0; r < BT; r++) {
            g_hn[(b0 + r) * Ll + l] = hs[r * Ll + l];
            g_cn[(b0 + r) * Ll + l] = cst[r];
        }
    }
}

// ------------------------- persistent decoder recurrence -------------------------
// Same structure on W_eff; per step emits out = h @ W_dense^T + b_dense at the
// flipped position. W_dense held in registers, quad-partitioned over latent dim,
// reduced with shfl_xor within each 4-lane quad.
__global__ void __launch_bounds__(TT, 1)
dec_kernel(const float* __restrict__ Wdn, const float* __restrict__ bdn,
           float* __restrict__ out) {
    extern __shared__ char smraw[];
    ulonglong2* Wsm = (ulonglong2*)smraw;            // 128KB
    float* hs = (float*)(smraw + 16 * 512 * 16);     // [4][128]
    float* us = hs + BT * Ll;                        // [4][128]
    const int t_ = threadIdx.x;
    const int b0 = blockIdx.x * BT;
    const int gA = t_, gB = t_ + 256;

    ull WrA[32], WrB[32];
    {
        const float4* wa = (const float4*)(g_weff + gA * Ll);
        const float4* wb = (const float4*)(g_weff + gB * Ll);
#pragma unroll
        for (int q = 0; q < 16; q++) {
            float4 v = wa[q]; WrA[2 * q] = pk(v.x, v.y); WrA[2 * q + 1] = pk(v.z, v.w);
            float4 u = wb[q]; WrB[2 * q] = pk(u.x, u.y); WrB[2 * q + 1] = pk(u.z, u.w);
        }
#pragma unroll
        for (int kg = 0; kg < 16; kg++) {
            ((float4*)Wsm)[kg * 512 + gA] = wa[16 + kg];
            ((float4*)Wsm)[kg * 512 + gB] = wb[16 + kg];
        }
    }
    // dense read-out: thread owns W_dense[fd][32*pd .. 32*pd+32) in registers
    const int fd = t_ >> 2, pd = t_ & 3;
    ull Wd[16];
    {
        const float4* wd = (const float4*)(Wdn + fd * Ll + 32 * pd);
#pragma unroll
        for (int i = 0; i < 8; i++) {
            float4 v = wd[i]; Wd[2 * i] = pk(v.x, v.y); Wd[2 * i + 1] = pk(v.z, v.w);
        }
    }
    const float bdv = bdn[fd];
    const float beA = g_beff[gA], beB = g_beff[gB];

    const bool isFO = (t_ >= 128);
    const int l = t_ & 127;
    // init h, c from encoder
    {
        int e1 = t_, e2 = t_ + 256;
        hs[e1] = g_hn[(b0 + (e1 >> 7)) * Ll + (e1 & 127)];
        hs[e2] = g_hn[(b0 + (e2 >> 7)) * Ll + (e2 & 127)];
    }
    float cst[BT];
#pragma unroll
    for (int r = 0; r < BT; r++) cst[r] = g_cn[(b0 + r) * Ll + l];  // used only by isFO
    __syncthreads();

    for (int t = 0; t < Ss; t++) {
        // dense read-out of current h (= H_t) -> out position S - t, for t >= 1
        if (t > 0) {
            float s[BT];
#pragma unroll
            for (int r = 0; r < BT; r++) {
                ull a = 0ull;
#pragma unroll
                for (int i = 0; i < 8; i++) {
                    ulonglong2 hh = *(const ulonglong2*)(hs + r * Ll + 32 * pd + 4 * i);
                    fma2(a, hh.x, Wd[2 * i]); fma2(a, hh.y, Wd[2 * i + 1]);
                }
                float lo, hi; upk(a, lo, hi); s[r] = lo + hi;
            }
#pragma unroll
            for (int r = 0; r < BT; r++) {
                s[r] += __shfl_xor_sync(0xffffffffu, s[r], 1);
                s[r] += __shfl_xor_sync(0xffffffffu, s[r], 2);
            }
            out[((size_t)(b0 + pd) * Ss + (Ss - t)) * Ff + fd] = s[pd] + bdv;
        }
        ull aA[BT] = {0ull, 0ull, 0ull, 0ull};
        ull aB[BT] = {0ull, 0ull, 0ull, 0ull};
#pragma unroll
        for (int q = 0; q < 16; q++) {
#pragma unroll
            for (int r = 0; r < BT; r++) {
                ulonglong2 hh = *(const ulonglong2*)(hs + r * Ll + 4 * q);
                fma2(aA[r], hh.x, WrA[2 * q]); fma2(aA[r], hh.y, WrA[2 * q + 1]);
                fma2(aB[r], hh.x, WrB[2 * q]); fma2(aB[r], hh.y, WrB[2 * q + 1]);
            }
        }
#pragma unroll
        for (int kg = 0; kg < 16; kg++) {
            ulonglong2 wAv = Wsm[kg * 512 + gA];
            ulonglong2 wBv = Wsm[kg * 512 + gB];
#pragma unroll
            for (int r = 0; r < BT; r++) {
                ulonglong2 hh = *(const ulonglong2*)(hs + r * Ll + 64 + 4 * kg);
                fma2(aA[r], hh.x, wAv.x); fma2(aA[r], hh.y, wAv.y);
                fma2(aB[r], hh.x, wBv.x); fma2(aB[r], hh.y, wBv.y);
            }
        }
        float sf[BT], so[BT];
#pragma unroll
        for (int r = 0; r < BT; r++) {
            float lo, hi, vA, vB;
            upk(aA[r], lo, hi); vA = lo + hi + beA;
            upk(aB[r], lo, hi); vB = lo + hi + beB;
            if (!isFO) {
                us[r * Ll + l] = fsig(vA) * ftanh(vB);
            } else {
                sf[r] = fsig(vA); so[r] = fsig(vB);
            }
        }
        __syncthreads();
        if (isFO) {
#pragma unroll
            for (int r = 0; r < BT; r++) {
                cst[r] = sf[r] * cst[r] + us[r * Ll + l];
                hs[r * Ll + l] = so[r] * ftanh(cst[r]);
            }
        }
        __syncthreads();
    }
    // final dense read-out (H_S) -> out position 0
    {
        float s[BT];
#pragma unroll
        for (int r = 0; r < BT; r++) {
            ull a = 0ull;
#pragma unroll
            for (int i = 0; i < 8; i++) {
                ulonglong2 hh = *(const ulonglong2*)(hs + r * Ll + 32 * pd + 4 * i);
                fma2(a, hh.x, Wd[2 * i]); fma2(a, hh.y, Wd[2 * i + 1]);
            }
            float lo, hi; upk(a, lo, hi); s[r] = lo + hi;
        }
#pragma unroll
        for (int r = 0; r < BT; r++) {
            s[r] += __shfl_xor_sync(0xffffffffu, s[r], 1);
            s[r] += __shfl_xor_sync(0xffffffffu, s[r], 2);
        }
        out[((size_t)(b0 + pd) * Ss + 0) * Ff + fd] = s[pd] + bdv;
    }
}

// ------------------------- launch -------------------------
extern "C" void kernel_launch(void* const* d_in, const int* in_sizes, int n_in,
                              void* d_out, int out_size) {
    const float* x     = (const float*)d_in[0];
    const float* Wih_e = (const float*)d_in[1];
    const float* Whh_e = (const float*)d_in[2];
    const float* bih_e = (const float*)d_in[3];
    const float* bhh_e = (const float*)d_in[4];
    const float* Wih_d = (const float*)d_in[5];
    const float* Whh_d = (const float*)d_in[6];
    const float* bih_d = (const float*)d_in[7];
    const float* bhh_d = (const float*)d_in[8];
    const float* Wdn   = (const float*)d_in[9];
    const float* bdn   = (const float*)d_in[10];
    float* out = (float*)d_out;

    const int SM_X = 16 * 512 * 16 + 32 * 64 * 4;                   // 139264
    const int SM_R = 16 * 512 * 16 + 2 * BT * Ll * 4;               // 135168

    cudaFuncSetAttribute(xproj_kernel, cudaFuncAttributeMaxDynamicSharedMemorySize, SM_X);
    cudaFuncSetAttribute(enc_kernel,   cudaFuncAttributeMaxDynamicSharedMemorySize, SM_R);
    cudaFuncSetAttribute(dec_kernel,   cudaFuncAttributeMaxDynamicSharedMemorySize, SM_R);

    setup_kernel<<<Gg, Ll>>>(Wih_d, Whh_d, bih_d, bhh_d, Wdn, bdn, bih_e, bhh_e);
    xproj_kernel<<<(Bb * Ss) / 32, TT, SM_X>>>(x, Wih_e);
    enc_kernel<<<Bb / BT, TT, SM_R>>>(Whh_e);
    dec_kernel<<<Bb / BT, TT, SM_R>>>(Wdn, bdn, out);
}